// round 14
// baseline (speedup 1.0000x reference)
#include <cuda_runtime.h>
#include <cstdint>
#include <cstddef>

// ============================================================================
// RNNSequence: h_t = tanh(x_t @ W_ih + h_{t-1} @ W_hh + b), out[b,t,:] = h_t
// B=32, T=2048, D_IN=512, D_H=512, fp32.
//
// Phase 1: gemm_xw writes xw = x@W_ih + b into d_out (reg-prefetch pipeline).
// Phase 2: rnn_scan: 64 CTAs = 8 groups x 8 ranks. Group g owns batches
//          {4g..4g+3} as two PAIRS, processed interleaved each step so each
//          pair's L2 exchange latency hides under the other pair's work.
//          Per pair the protocol is EXACTLY R8 (proven): 8-lane flag poll ->
//          stage 4KB -> compute (W_hh slice in registers) -> publish ->
//          release. Monotonic flags (graph-replay safe), t=0 uses h=0.
// ============================================================================

constexpr int SEQ = 2048;
constexpr int DH  = 512;

// L2-resident exchange state. g_h needs no init (t=0 reads nothing; t>=1 reads
// only same-launch data). g_flag zero-init, only grows (graph-replay safe).
__device__ __align__(16) float g_h[2][2][8][8][2][64];
// [pair][buf][group][rank][batch][j]
__device__ unsigned g_flag[2][8][32];   // [pair][group][rank], padded rows

__device__ __forceinline__ unsigned long long pack2(float lo, float hi) {
    unsigned long long r;
    unsigned l = __float_as_uint(lo), h = __float_as_uint(hi);
    asm("mov.b64 %0, {%1, %2};" : "=l"(r) : "r"(l), "r"(h));
    return r;
}
__device__ __forceinline__ void unpack2(unsigned long long v, float& lo, float& hi) {
    unsigned l, h;
    asm("mov.b64 {%0, %1}, %2;" : "=r"(l), "=r"(h) : "l"(v));
    lo = __uint_as_float(l);
    hi = __uint_as_float(h);
}
__device__ __forceinline__ void fma2(unsigned long long& acc,
                                     unsigned long long a, unsigned long long b) {
    asm("fma.rn.f32x2 %0, %1, %2, %0;" : "+l"(acc) : "l"(a), "l"(b));
}

// ---------------------------------------------------------------------------
// Phase 1: C[M,512] = A[M,512] @ B[512,512] + bias (128x128x16, reg-prefetch)
// ---------------------------------------------------------------------------
__global__ __launch_bounds__(256, 2) void gemm_xw(const float* __restrict__ A,
                                                  const float* __restrict__ B,
                                                  const float* __restrict__ bias,
                                                  float* __restrict__ C) {
    constexpr int K = 512, N = 512;
    __shared__ __align__(16) float As[16][128];
    __shared__ __align__(16) float Bs[16][128];

    const int tid  = threadIdx.x;
    const int row0 = blockIdx.y * 128;
    const int col0 = blockIdx.x * 128;
    const int ty   = tid >> 4;
    const int tx   = tid & 15;

    const int m0  = tid & 127;
    const int m1  = (tid + 256) & 127;
    const int kg0 = ((tid) >> 7) << 2;
    const int kg1 = ((tid + 256) >> 7) << 2;
    const int bn0 = (tid & 31) << 2;
    const int bk0 = tid >> 5;
    const int bn1 = ((tid + 256) & 31) << 2;
    const int bk1 = (tid + 256) >> 5;

    float4 rA0, rA1, rB0, rB1;
    rA0 = *(const float4*)(A + (size_t)(row0 + m0) * K + kg0);
    rA1 = *(const float4*)(A + (size_t)(row0 + m1) * K + kg1);
    rB0 = *(const float4*)(B + (size_t)bk0 * N + col0 + bn0);
    rB1 = *(const float4*)(B + (size_t)bk1 * N + col0 + bn1);

    unsigned long long acc2[8][4];
#pragma unroll
    for (int i = 0; i < 8; i++)
#pragma unroll
        for (int j = 0; j < 4; j++) acc2[i][j] = 0ULL;

    for (int k0 = 0; k0 < K; k0 += 16) {
        As[kg0 + 0][m0] = rA0.x; As[kg0 + 1][m0] = rA0.y;
        As[kg0 + 2][m0] = rA0.z; As[kg0 + 3][m0] = rA0.w;
        As[kg1 + 0][m1] = rA1.x; As[kg1 + 1][m1] = rA1.y;
        As[kg1 + 2][m1] = rA1.z; As[kg1 + 3][m1] = rA1.w;
        *(float4*)(&Bs[bk0][bn0]) = rB0;
        *(float4*)(&Bs[bk1][bn1]) = rB1;
        __syncthreads();

        if (k0 + 16 < K) {
            rA0 = *(const float4*)(A + (size_t)(row0 + m0) * K + (k0 + 16 + kg0));
            rA1 = *(const float4*)(A + (size_t)(row0 + m1) * K + (k0 + 16 + kg1));
            rB0 = *(const float4*)(B + (size_t)(k0 + 16 + bk0) * N + col0 + bn0);
            rB1 = *(const float4*)(B + (size_t)(k0 + 16 + bk1) * N + col0 + bn1);
        }

#pragma unroll
        for (int kk = 0; kk < 16; kk++) {
            float a[8];
            *(float4*)(a)     = *(const float4*)(&As[kk][ty * 8]);
            *(float4*)(a + 4) = *(const float4*)(&As[kk][ty * 8 + 4]);
            ulonglong2 b01 = *(const ulonglong2*)(&Bs[kk][tx * 8]);
            ulonglong2 b23 = *(const ulonglong2*)(&Bs[kk][tx * 8 + 4]);
            unsigned long long bb[4] = {b01.x, b01.y, b23.x, b23.y};
#pragma unroll
            for (int i = 0; i < 8; i++) {
                unsigned au = __float_as_uint(a[i]);
                unsigned long long ad;
                asm("mov.b64 %0, {%1, %1};" : "=l"(ad) : "r"(au));
#pragma unroll
                for (int j2 = 0; j2 < 4; j2++) fma2(acc2[i][j2], ad, bb[j2]);
            }
        }
        __syncthreads();
    }

    float bv[8];
    *(float4*)(bv)     = *(const float4*)(bias + col0 + tx * 8);
    *(float4*)(bv + 4) = *(const float4*)(bias + col0 + tx * 8 + 4);

#pragma unroll
    for (int i = 0; i < 8; i++) {
        float o[8];
#pragma unroll
        for (int j2 = 0; j2 < 4; j2++) {
            float lo, hi;
            unpack2(acc2[i][j2], lo, hi);
            o[j2 * 2]     = lo + bv[j2 * 2];
            o[j2 * 2 + 1] = hi + bv[j2 * 2 + 1];
        }
        float* cp = C + (size_t)(row0 + ty * 8 + i) * N + col0 + tx * 8;
        *(float4*)(cp)     = *(float4*)(o);
        *(float4*)(cp + 4) = *(float4*)(o + 4);
    }
}

// ---------------------------------------------------------------------------
// Phase 2: L2 flag-pipelined scan, two interleaved batch-pairs per group
// ---------------------------------------------------------------------------
constexpr int RSTRIDE = 132;   // smem rank stride (floats): conflict-free phases

// Fast tanh: MUFU-based (EX2 + RCP). Abs err ~1e-7; deterministic.
__device__ __forceinline__ float tanh_fast(float x) {
    float e = __expf(2.0f * fabsf(x));            // inf for large x -> r = 1
    float r = 1.0f - __fdividef(2.0f, e + 1.0f);
    return copysignf(r, x);
}

__device__ __forceinline__ unsigned ld_acquire_gpu(const unsigned* p) {
    unsigned v;
    asm volatile("ld.acquire.gpu.u32 %0, [%1];" : "=r"(v) : "l"(p) : "memory");
    return v;
}
__device__ __forceinline__ void st_release_gpu(unsigned* p, unsigned v) {
    asm volatile("st.release.gpu.u32 [%0], %1;" :: "l"(p), "r"(v) : "memory");
}

__global__ __launch_bounds__(256, 1) void rnn_scan(float* __restrict__ out,
                                                   const float* __restrict__ Whh) {
    __shared__ __align__(16) float hs[2][8 * RSTRIDE];   // [pair][...]

    const int tid = threadIdx.x;
    const int r   = blockIdx.x & 7;     // rank in group
    const int g   = blockIdx.x >> 3;    // group id (0..7)

    const int j   = tid >> 2;           // 0..63
    const int kq  = tid & 3;            // 0..3
    const int col = r * 64 + j;
    const int k0  = kq * 128;

    // W_hh slice in registers: w2[i] = (Whh[k0+2i][col], Whh[k0+2i+1][col])
    unsigned long long w2[64];
#pragma unroll
    for (int i = 0; i < 64; i++) {
        float lo = Whh[(size_t)(k0 + 2 * i)     * 512 + col];
        float hi = Whh[(size_t)(k0 + 2 * i + 1) * 512 + col];
        w2[i] = pack2(lo, hi);
    }

    // Per-pair monotonic flag bases (quiescent at launch).
    const unsigned base0 = *(volatile unsigned*)&g_flag[0][g][r];
    const unsigned base1 = *(volatile unsigned*)&g_flag[1][g][r];
    unsigned* const flags0 = &g_flag[0][g][0];
    unsigned* const flags1 = &g_flag[1][g][0];

    // writer role: kq==0 -> first batch of pair, kq==1 -> second
    const int batch = (kq < 2) ? kq : 0;
    float* outp0 = out + ((size_t)(g * 4 + batch)     * SEQ) * DH + col;
    float* outp1 = out + ((size_t)(g * 4 + 2 + batch) * SEQ) * DH + col;

    // publish bases: g_h[pair][buf][g][r][0][0]
    float* const hw00 = &g_h[0][0][g][r][0][0];
    float* const hw01 = &g_h[0][1][g][r][0][0];
    float* const hw10 = &g_h[1][0][g][r][0][0];
    float* const hw11 = &g_h[1][1][g][r][0][0];

    // stage role: warp w stages rank w's 512B block, 16B per lane
    const int srank = tid >> 5;
    const int sw    = tid & 31;
    const float4* const s00 = (const float4*)&g_h[0][0][g][0][0][0] + tid;
    const float4* const s01 = (const float4*)&g_h[0][1][g][0][0][0] + tid;
    const float4* const s10 = (const float4*)&g_h[1][0][g][0][0][0] + tid;
    const float4* const s11 = (const float4*)&g_h[1][1][g][0][0][0] + tid;
    const int sdoff = srank * RSTRIDE + sw * 4;

    // xw prefetch pipelines (one step ahead, per pair)
    float xw0_next = 0.0f, xw1_next = 0.0f;
    if (kq < 2) {
        xw0_next = __ldg(outp0);
        xw1_next = __ldg(outp1);
    }

    // One pair's full R8-protocol step. E of this pair's exchange hides under
    // the other pair's invocation of this same block.
    auto pair_step = [&](int t, unsigned base, unsigned* flags,
                         const float4* sA, const float4* sB, float* hsP,
                         float* hwA, float* hwB, float* outp, float& xw_next) {
        const int cur = t & 1;

        float xwv = xw_next;
        if (kq < 2 && t + 1 < SEQ) xw_next = __ldg(outp + (size_t)(t + 1) * DH);

        float sum = 0.0f;
        if (t > 0) {
            if (tid < 8) {
                const unsigned target = base + (unsigned)t;
                while ((int)(ld_acquire_gpu(flags + tid) - target) < 0) {}
            }
            __syncthreads();
            float4 v = __ldcg(cur ? sB : sA);
            *(float4*)(hsP + sdoff) = v;
            __syncthreads();

            const ulonglong2* pa0 = (const ulonglong2*)(hsP + (2 * kq)     * RSTRIDE);
            const ulonglong2* pa1 = (const ulonglong2*)(hsP + (2 * kq + 1) * RSTRIDE);
            const ulonglong2* pb0 = (const ulonglong2*)(hsP + (2 * kq)     * RSTRIDE + 64);
            const ulonglong2* pb1 = (const ulonglong2*)(hsP + (2 * kq + 1) * RSTRIDE + 64);

            unsigned long long aA0 = 0ULL, aA1 = 0ULL, aB0 = 0ULL, aB1 = 0ULL;
#pragma unroll
            for (int i = 0; i < 16; i++) {
                ulonglong2 xa = pa0[i];
                ulonglong2 xb = pa1[i];
                ulonglong2 ya = pb0[i];
                ulonglong2 yb = pb1[i];
                fma2(aA0, w2[2 * i],          xa.x);
                fma2(aA0, w2[2 * i + 1],      xa.y);
                fma2(aA1, w2[32 + 2 * i],     xb.x);
                fma2(aA1, w2[32 + 2 * i + 1], xb.y);
                fma2(aB0, w2[2 * i],          ya.x);
                fma2(aB0, w2[2 * i + 1],      ya.y);
                fma2(aB1, w2[32 + 2 * i],     yb.x);
                fma2(aB1, w2[32 + 2 * i + 1], yb.y);
            }
            float a0l, a0h, a1l, a1h, b0l, b0h, b1l, b1h;
            unpack2(aA0, a0l, a0h);
            unpack2(aA1, a1l, a1h);
            unpack2(aB0, b0l, b0h);
            unpack2(aB1, b1l, b1h);
            float pA = (a0l + a0h) + (a1l + a1h);
            float pB = (b0l + b0h) + (b1l + b1h);
            float u  = (kq & 1) ? pB : pA;
            float v2 = (kq & 1) ? pA : pB;
            u += __shfl_xor_sync(0xffffffffu, v2, 1);
            u += __shfl_xor_sync(0xffffffffu, u, 2);
            sum = u;
        }

        float hn = 0.0f;
        if (kq < 2) {
            hn = tanh_fast(sum + xwv);                     // t==0: sum=0
            if (t < SEQ - 1) {
                float* hwN = (cur ? hwA : hwB);            // buf (t+1)&1
                __stcg(hwN + kq * 64 + j, hn);             // publish FIRST
            }
        }
        if (t < SEQ - 1) {
            __syncthreads();
            if (tid == 0)
                st_release_gpu(flags + r, base + (unsigned)(t + 1));
        }
        if (kq < 2) outp[(size_t)t * DH] = hn;             // off critical path
    };

    for (int t = 0; t < SEQ; ++t) {
        pair_step(t, base0, flags0, s00, s01, hs[0], hw00, hw01, outp0, xw0_next);
        pair_step(t, base1, flags1, s10, s11, hs[1], hw10, hw11, outp1, xw1_next);
    }
}

// ---------------------------------------------------------------------------
// Launch
// ---------------------------------------------------------------------------
extern "C" void kernel_launch(void* const* d_in, const int* in_sizes, int n_in,
                              void* d_out, int out_size) {
    const float* x    = (const float*)d_in[0];  // [32,2048,512]
    const float* W_ih = (const float*)d_in[1];  // [512,512]
    const float* W_hh = (const float*)d_in[2];  // [512,512]
    const float* bias = (const float*)d_in[3];  // [512]
    float* out = (float*)d_out;                 // [32,2048,512]

    dim3 ggrid(512 / 128, (32 * SEQ) / 128);    // (4, 512)
    gemm_xw<<<ggrid, 256>>>(x, W_ih, bias, out);

    // 64 CTAs = 8 groups x 8 ranks (single wave — required for spin safety).
    rnn_scan<<<64, 256>>>(out, W_hh);
}

// round 16
// speedup vs baseline: 1.2403x; 1.2403x over previous
#include <cuda_runtime.h>
#include <cstdint>
#include <cstddef>

// ============================================================================
// RNNSequence: h_t = tanh(x_t @ W_ih + h_{t-1} @ W_hh + b), out[b,t,:] = h_t
// B=32, T=2048, D_IN=512, D_H=512, fp32.
//
// Phase 1: gemm_xw writes xw = x@W_ih + b into d_out (reg-prefetch pipeline).
// Phase 2: rnn_scan (R8 protocol, 512-thread shape): 128 CTAs = 16 groups x
//          8 ranks. Thread = (j, ko): j in [0,64) output col within slice,
//          ko in [0,8) k-eighth (64 k each). W_hh slice in registers
//          (32 f32x2/thread). L2 flag exchange per R8: ACQUIRE poll ->
//          stage 4KB -> compute -> publish -> release. 16 warps/CTA for
//          latency hiding. Monotonic flags (graph-replay safe).
//          R15 fix: poll restored to ld.acquire.gpu (relaxed .cg polling is
//          unsound: post-poll data loads can merge with older in-flight
//          requests for the same line and return stale sectors).
// ============================================================================

constexpr int SEQ = 2048;
constexpr int DH  = 512;

// L2-resident exchange state. g_h needs no init (t=0 reads nothing; t>=1 reads
// only same-launch data). g_flag zero-init, only grows (graph-replay safe).
__device__ __align__(16) float g_h[2][16][8][2][64]; // [buf][grp][rank][batch][j]
__device__ unsigned g_flag[16][32];                   // [group][rank], padded row

__device__ __forceinline__ unsigned long long pack2(float lo, float hi) {
    unsigned long long r;
    unsigned l = __float_as_uint(lo), h = __float_as_uint(hi);
    asm("mov.b64 %0, {%1, %2};" : "=l"(r) : "r"(l), "r"(h));
    return r;
}
__device__ __forceinline__ void unpack2(unsigned long long v, float& lo, float& hi) {
    unsigned l, h;
    asm("mov.b64 {%0, %1}, %2;" : "=r"(l), "=r"(h) : "l"(v));
    lo = __uint_as_float(l);
    hi = __uint_as_float(h);
}
__device__ __forceinline__ void fma2(unsigned long long& acc,
                                     unsigned long long a, unsigned long long b) {
    asm("fma.rn.f32x2 %0, %1, %2, %0;" : "+l"(acc) : "l"(a), "l"(b));
}

// ---------------------------------------------------------------------------
// Phase 1: C[M,512] = A[M,512] @ B[512,512] + bias (128x128x16, reg-prefetch)
// ---------------------------------------------------------------------------
__global__ __launch_bounds__(256, 2) void gemm_xw(const float* __restrict__ A,
                                                  const float* __restrict__ B,
                                                  const float* __restrict__ bias,
                                                  float* __restrict__ C) {
    constexpr int K = 512, N = 512;
    __shared__ __align__(16) float As[16][128];
    __shared__ __align__(16) float Bs[16][128];

    const int tid  = threadIdx.x;
    const int row0 = blockIdx.y * 128;
    const int col0 = blockIdx.x * 128;
    const int ty   = tid >> 4;
    const int tx   = tid & 15;

    const int m0  = tid & 127;
    const int m1  = (tid + 256) & 127;
    const int kg0 = ((tid) >> 7) << 2;
    const int kg1 = ((tid + 256) >> 7) << 2;
    const int bn0 = (tid & 31) << 2;
    const int bk0 = tid >> 5;
    const int bn1 = ((tid + 256) & 31) << 2;
    const int bk1 = (tid + 256) >> 5;

    float4 rA0, rA1, rB0, rB1;
    rA0 = *(const float4*)(A + (size_t)(row0 + m0) * K + kg0);
    rA1 = *(const float4*)(A + (size_t)(row0 + m1) * K + kg1);
    rB0 = *(const float4*)(B + (size_t)bk0 * N + col0 + bn0);
    rB1 = *(const float4*)(B + (size_t)bk1 * N + col0 + bn1);

    unsigned long long acc2[8][4];
#pragma unroll
    for (int i = 0; i < 8; i++)
#pragma unroll
        for (int j = 0; j < 4; j++) acc2[i][j] = 0ULL;

    for (int k0 = 0; k0 < K; k0 += 16) {
        As[kg0 + 0][m0] = rA0.x; As[kg0 + 1][m0] = rA0.y;
        As[kg0 + 2][m0] = rA0.z; As[kg0 + 3][m0] = rA0.w;
        As[kg1 + 0][m1] = rA1.x; As[kg1 + 1][m1] = rA1.y;
        As[kg1 + 2][m1] = rA1.z; As[kg1 + 3][m1] = rA1.w;
        *(float4*)(&Bs[bk0][bn0]) = rB0;
        *(float4*)(&Bs[bk1][bn1]) = rB1;
        __syncthreads();

        if (k0 + 16 < K) {
            rA0 = *(const float4*)(A + (size_t)(row0 + m0) * K + (k0 + 16 + kg0));
            rA1 = *(const float4*)(A + (size_t)(row0 + m1) * K + (k0 + 16 + kg1));
            rB0 = *(const float4*)(B + (size_t)(k0 + 16 + bk0) * N + col0 + bn0);
            rB1 = *(const float4*)(B + (size_t)(k0 + 16 + bk1) * N + col0 + bn1);
        }

#pragma unroll
        for (int kk = 0; kk < 16; kk++) {
            float a[8];
            *(float4*)(a)     = *(const float4*)(&As[kk][ty * 8]);
            *(float4*)(a + 4) = *(const float4*)(&As[kk][ty * 8 + 4]);
            ulonglong2 b01 = *(const ulonglong2*)(&Bs[kk][tx * 8]);
            ulonglong2 b23 = *(const ulonglong2*)(&Bs[kk][tx * 8 + 4]);
            unsigned long long bb[4] = {b01.x, b01.y, b23.x, b23.y};
#pragma unroll
            for (int i = 0; i < 8; i++) {
                unsigned au = __float_as_uint(a[i]);
                unsigned long long ad;
                asm("mov.b64 %0, {%1, %1};" : "=l"(ad) : "r"(au));
#pragma unroll
                for (int j2 = 0; j2 < 4; j2++) fma2(acc2[i][j2], ad, bb[j2]);
            }
        }
        __syncthreads();
    }

    float bv[8];
    *(float4*)(bv)     = *(const float4*)(bias + col0 + tx * 8);
    *(float4*)(bv + 4) = *(const float4*)(bias + col0 + tx * 8 + 4);

#pragma unroll
    for (int i = 0; i < 8; i++) {
        float o[8];
#pragma unroll
        for (int j2 = 0; j2 < 4; j2++) {
            float lo, hi;
            unpack2(acc2[i][j2], lo, hi);
            o[j2 * 2]     = lo + bv[j2 * 2];
            o[j2 * 2 + 1] = hi + bv[j2 * 2 + 1];
        }
        float* cp = C + (size_t)(row0 + ty * 8 + i) * N + col0 + tx * 8;
        *(float4*)(cp)     = *(float4*)(o);
        *(float4*)(cp + 4) = *(float4*)(o + 4);
    }
}

// ---------------------------------------------------------------------------
// Phase 2: L2 flag-pipelined scan, 512 threads, 8-way k split
// ---------------------------------------------------------------------------
constexpr int RSTRIDE = 132;   // smem rank stride (floats)

// Fast tanh: MUFU-based (EX2 + RCP). Abs err ~1e-7; deterministic.
__device__ __forceinline__ float tanh_fast(float x) {
    float e = __expf(2.0f * fabsf(x));            // inf for large x -> r = 1
    float r = 1.0f - __fdividef(2.0f, e + 1.0f);
    return copysignf(r, x);
}

__device__ __forceinline__ unsigned ld_acquire_gpu(const unsigned* p) {
    unsigned v;
    asm volatile("ld.acquire.gpu.u32 %0, [%1];" : "=r"(v) : "l"(p) : "memory");
    return v;
}
__device__ __forceinline__ void st_release_gpu(unsigned* p, unsigned v) {
    asm volatile("st.release.gpu.u32 [%0], %1;" :: "l"(p), "r"(v) : "memory");
}

__global__ __launch_bounds__(512, 1) void rnn_scan(float* __restrict__ out,
                                                   const float* __restrict__ Whh) {
    __shared__ __align__(16) float hs[8 * RSTRIDE];

    const int tid = threadIdx.x;
    const int r   = blockIdx.x & 7;     // rank in group
    const int g   = blockIdx.x >> 3;    // group id (0..15)

    const int j   = tid >> 3;           // 0..63  col within slice
    const int ko  = tid & 7;            // 0..7   k-eighth (64 k each)
    const int col = r * 64 + j;
    const int k0  = ko * 64;

    // W_hh slice in registers: w2[i] = (Whh[k0+2i][col], Whh[k0+2i+1][col])
    unsigned long long w2[32];
#pragma unroll
    for (int i = 0; i < 32; i++) {
        float lo = Whh[(size_t)(k0 + 2 * i)     * 512 + col];
        float hi = Whh[(size_t)(k0 + 2 * i + 1) * 512 + col];
        w2[i] = pack2(lo, hi);
    }

    // Monotonic flag base: quiescent at launch; only this CTA writes its flag.
    const unsigned base = *(volatile unsigned*)&g_flag[g][r];
    unsigned* const flags = &g_flag[g][0];

    // writer role: ko==0 -> batch 2g, ko==1 -> batch 2g+1
    const int batch = (ko < 2) ? ko : 0;
    float* outp = out + ((size_t)(g * 2 + batch) * SEQ) * DH + col;
    float* const hw[2] = { &g_h[0][g][r][0][0], &g_h[1][g][r][0][0] };

    // stage role (tid<256): warp w stages rank w's 512B block, 16B per lane
    const int srank = (tid >> 5) & 7;
    const int sw    = tid & 31;
    const float4* const ssrc[2] = {
        (const float4*)&g_h[0][g][0][0][0] + tid,
        (const float4*)&g_h[1][g][0][0][0] + tid
    };
    float* const sdst = (float*)hs + srank * RSTRIDE + sw * 4;

    // xw prefetch pipeline (one step ahead)
    float xw_next = 0.0f;
    if (ko < 2) xw_next = __ldg(outp);

    // compute source pointers: k range [64ko, 64ko+64) == rank ko's block
    const ulonglong2* const pa = (const ulonglong2*)(hs + ko * RSTRIDE);      // batch0
    const ulonglong2* const pb = (const ulonglong2*)(hs + ko * RSTRIDE + 64); // batch1

    for (int t = 0; t < SEQ; ++t) {
        const int cur = t & 1;
        const int nb  = cur ^ 1;

        float xwv = xw_next;
        if (ko < 2 && t + 1 < SEQ) xw_next = __ldg(outp + (size_t)(t + 1) * DH);

        float sum = 0.0f;
        if (t > 0) {
            // Wait: all 8 ranks published o_{t-1} (flag >= base+t).
            // ACQUIRE is load-bearing: it forbids post-poll data loads from
            // merging with older in-flight requests (stale-sector hazard).
            if (tid < 8) {
                const unsigned target = base + (unsigned)t;
                while ((int)(ld_acquire_gpu(flags + tid) - target) < 0) {}
            }
            __syncthreads();
            // Stage 4KB of o_{t-1} from L2 into padded smem (tid<256).
            if (tid < 256) {
                float4 v = __ldcg(ssrc[cur]);
                *(float4*)sdst = v;
            }
            __syncthreads();

            unsigned long long aA0 = 0ULL, aA1 = 0ULL, aB0 = 0ULL, aB1 = 0ULL;
#pragma unroll
            for (int i = 0; i < 8; i++) {
                ulonglong2 xa0 = pa[2 * i];
                ulonglong2 xa1 = pa[2 * i + 1];
                ulonglong2 yb0 = pb[2 * i];
                ulonglong2 yb1 = pb[2 * i + 1];
                fma2(aA0, w2[4 * i + 0], xa0.x);
                fma2(aA0, w2[4 * i + 1], xa0.y);
                fma2(aA1, w2[4 * i + 2], xa1.x);
                fma2(aA1, w2[4 * i + 3], xa1.y);
                fma2(aB0, w2[4 * i + 0], yb0.x);
                fma2(aB0, w2[4 * i + 1], yb0.y);
                fma2(aB1, w2[4 * i + 2], yb1.x);
                fma2(aB1, w2[4 * i + 3], yb1.y);
            }
            float a0l, a0h, a1l, a1h, b0l, b0h, b1l, b1h;
            unpack2(aA0, a0l, a0h);
            unpack2(aA1, a1l, a1h);
            unpack2(aB0, b0l, b0h);
            unpack2(aB1, b1l, b1h);
            float pA = (a0l + a0h) + (a1l + a1h);
            float pB = (b0l + b0h) + (b1l + b1h);
            // paired reduction over 8 ko lanes: after this, ko==0 lane holds
            // the full batch-0 sum, ko==1 lane the full batch-1 sum.
            float u  = (ko & 1) ? pB : pA;
            float v2 = (ko & 1) ? pA : pB;
            u += __shfl_xor_sync(0xffffffffu, v2, 1);
            u += __shfl_xor_sync(0xffffffffu, u, 2);
            u += __shfl_xor_sync(0xffffffffu, u, 4);
            sum = u;
        }

        float hn = 0.0f;
        if (ko < 2) {
            hn = tanh_fast(sum + xwv);              // t==0: sum=0
            if (t < SEQ - 1)
                __stcg(hw[nb] + ko * 64 + j, hn);   // publish FIRST (critical)
        }

        if (t < SEQ - 1) {
            __syncthreads();   // all publish stores issued CTA-wide
            if (tid == 0)
                st_release_gpu(flags + r, base + (unsigned)(t + 1));
        }

        // DRAM output store AFTER the release: off the critical path.
        if (ko < 2) outp[(size_t)t * DH] = hn;
    }
}

// ---------------------------------------------------------------------------
// Launch
// ---------------------------------------------------------------------------
extern "C" void kernel_launch(void* const* d_in, const int* in_sizes, int n_in,
                              void* d_out, int out_size) {
    const float* x    = (const float*)d_in[0];  // [32,2048,512]
    const float* W_ih = (const float*)d_in[1];  // [512,512]
    const float* W_hh = (const float*)d_in[2];  // [512,512]
    const float* bias = (const float*)d_in[3];  // [512]
    float* out = (float*)d_out;                 // [32,2048,512]

    dim3 ggrid(512 / 128, (32 * SEQ) / 128);    // (4, 512)
    gemm_xw<<<ggrid, 256>>>(x, W_ih, bias, out);

    // 128 CTAs = 16 groups x 8 ranks (single wave — required for spin safety).
    rnn_scan<<<128, 512>>>(out, W_hh);
}

// round 17
// speedup vs baseline: 2.0351x; 1.6409x over previous
#include <cuda_runtime.h>
#include <cstdint>
#include <cstddef>

// ============================================================================
// RNNSequence: h_t = tanh(x_t @ W_ih + h_{t-1} @ W_hh + b), out[b,t,:] = h_t
// B=32, T=2048, D_IN=512, D_H=512, fp32.
//
// Phase 1: gemm_xw PERSISTENT: 296 CTAs (2/SM x 148), each loops over ~7
//          128x128 tiles (reg-prefetch pipeline inside each tile). Removes
//          wave quantization (2048 CTAs / 296 = 6.92 waves in the old form).
// Phase 2: rnn_scan — EXACT R13 configuration (best measured: 4773us):
//          128 CTAs = 16 groups x 8 ranks, 256 thr; W_hh slice in registers
//          (64 f32x2/thread); L2 flag exchange: 8-lane ACQUIRE poll -> stage
//          4KB -> compute -> publish -> release; fast tanh; 3-shuffle paired
//          reduction; DRAM out-store after the release. Monotonic flags.
// ============================================================================

constexpr int SEQ = 2048;
constexpr int DH  = 512;

// L2-resident exchange state. g_h needs no init (t=0 reads nothing; t>=1 reads
// only same-launch data). g_flag zero-init, only grows (graph-replay safe).
__device__ __align__(16) float g_h[2][16][8][2][64]; // [buf][grp][rank][batch][j]
__device__ unsigned g_flag[16][32];                   // [group][rank], padded row

__device__ __forceinline__ unsigned long long pack2(float lo, float hi) {
    unsigned long long r;
    unsigned l = __float_as_uint(lo), h = __float_as_uint(hi);
    asm("mov.b64 %0, {%1, %2};" : "=l"(r) : "r"(l), "r"(h));
    return r;
}
__device__ __forceinline__ void unpack2(unsigned long long v, float& lo, float& hi) {
    unsigned l, h;
    asm("mov.b64 {%0, %1}, %2;" : "=r"(l), "=r"(h) : "l"(v));
    lo = __uint_as_float(l);
    hi = __uint_as_float(h);
}
__device__ __forceinline__ void fma2(unsigned long long& acc,
                                     unsigned long long a, unsigned long long b) {
    asm("fma.rn.f32x2 %0, %1, %2, %0;" : "+l"(acc) : "l"(a), "l"(b));
}

// ---------------------------------------------------------------------------
// Phase 1: persistent GEMM, C[M,512] = A[M,512] @ B[512,512] + bias
// ---------------------------------------------------------------------------
constexpr int GEMM_CTAS  = 296;             // 2 per SM x 148
constexpr int GEMM_TILES = 2048;            // (65536/128) * (512/128)

__global__ __launch_bounds__(256, 2) void gemm_xw(const float* __restrict__ A,
                                                  const float* __restrict__ B,
                                                  const float* __restrict__ bias,
                                                  float* __restrict__ C) {
    constexpr int K = 512, N = 512;
    __shared__ __align__(16) float As[16][128];
    __shared__ __align__(16) float Bs[16][128];

    const int tid = threadIdx.x;
    const int ty  = tid >> 4;
    const int tx  = tid & 15;

    const int m0  = tid & 127;
    const int m1  = (tid + 256) & 127;
    const int kg0 = ((tid) >> 7) << 2;
    const int kg1 = ((tid + 256) >> 7) << 2;
    const int bn0 = (tid & 31) << 2;
    const int bk0 = tid >> 5;
    const int bn1 = ((tid + 256) & 31) << 2;
    const int bk1 = (tid + 256) >> 5;

    for (int s = blockIdx.x; s < GEMM_TILES; s += GEMM_CTAS) {
        const int row0 = (s >> 2) * 128;
        const int col0 = (s & 3) * 128;

        float4 rA0, rA1, rB0, rB1;
        rA0 = *(const float4*)(A + (size_t)(row0 + m0) * K + kg0);
        rA1 = *(const float4*)(A + (size_t)(row0 + m1) * K + kg1);
        rB0 = *(const float4*)(B + (size_t)bk0 * N + col0 + bn0);
        rB1 = *(const float4*)(B + (size_t)bk1 * N + col0 + bn1);

        unsigned long long acc2[8][4];
#pragma unroll
        for (int i = 0; i < 8; i++)
#pragma unroll
            for (int j = 0; j < 4; j++) acc2[i][j] = 0ULL;

        for (int k0 = 0; k0 < K; k0 += 16) {
            As[kg0 + 0][m0] = rA0.x; As[kg0 + 1][m0] = rA0.y;
            As[kg0 + 2][m0] = rA0.z; As[kg0 + 3][m0] = rA0.w;
            As[kg1 + 0][m1] = rA1.x; As[kg1 + 1][m1] = rA1.y;
            As[kg1 + 2][m1] = rA1.z; As[kg1 + 3][m1] = rA1.w;
            *(float4*)(&Bs[bk0][bn0]) = rB0;
            *(float4*)(&Bs[bk1][bn1]) = rB1;
            __syncthreads();

            if (k0 + 16 < K) {
                rA0 = *(const float4*)(A + (size_t)(row0 + m0) * K + (k0 + 16 + kg0));
                rA1 = *(const float4*)(A + (size_t)(row0 + m1) * K + (k0 + 16 + kg1));
                rB0 = *(const float4*)(B + (size_t)(k0 + 16 + bk0) * N + col0 + bn0);
                rB1 = *(const float4*)(B + (size_t)(k0 + 16 + bk1) * N + col0 + bn1);
            }

#pragma unroll
            for (int kk = 0; kk < 16; kk++) {
                float a[8];
                *(float4*)(a)     = *(const float4*)(&As[kk][ty * 8]);
                *(float4*)(a + 4) = *(const float4*)(&As[kk][ty * 8 + 4]);
                ulonglong2 b01 = *(const ulonglong2*)(&Bs[kk][tx * 8]);
                ulonglong2 b23 = *(const ulonglong2*)(&Bs[kk][tx * 8 + 4]);
                unsigned long long bb[4] = {b01.x, b01.y, b23.x, b23.y};
#pragma unroll
                for (int i = 0; i < 8; i++) {
                    unsigned au = __float_as_uint(a[i]);
                    unsigned long long ad;
                    asm("mov.b64 %0, {%1, %1};" : "=l"(ad) : "r"(au));
#pragma unroll
                    for (int j2 = 0; j2 < 4; j2++) fma2(acc2[i][j2], ad, bb[j2]);
                }
            }
            __syncthreads();
        }

        float bv[8];
        *(float4*)(bv)     = *(const float4*)(bias + col0 + tx * 8);
        *(float4*)(bv + 4) = *(const float4*)(bias + col0 + tx * 8 + 4);

#pragma unroll
        for (int i = 0; i < 8; i++) {
            float o[8];
#pragma unroll
            for (int j2 = 0; j2 < 4; j2++) {
                float lo, hi;
                unpack2(acc2[i][j2], lo, hi);
                o[j2 * 2]     = lo + bv[j2 * 2];
                o[j2 * 2 + 1] = hi + bv[j2 * 2 + 1];
            }
            float* cp = C + (size_t)(row0 + ty * 8 + i) * N + col0 + tx * 8;
            *(float4*)(cp)     = *(float4*)(o);
            *(float4*)(cp + 4) = *(float4*)(o + 4);
        }
        __syncthreads();   // As/Bs safe to refill for the next tile
    }
}

// ---------------------------------------------------------------------------
// Phase 2: L2 flag-pipelined scan (R13/R8 protocol — best measured)
// ---------------------------------------------------------------------------
constexpr int RSTRIDE = 132;   // smem rank stride (floats): conflict-free phases

// Fast tanh: MUFU-based (EX2 + RCP). Abs err ~1e-7; deterministic.
__device__ __forceinline__ float tanh_fast(float x) {
    float e = __expf(2.0f * fabsf(x));            // inf for large x -> r = 1
    float r = 1.0f - __fdividef(2.0f, e + 1.0f);
    return copysignf(r, x);
}

__device__ __forceinline__ unsigned ld_acquire_gpu(const unsigned* p) {
    unsigned v;
    asm volatile("ld.acquire.gpu.u32 %0, [%1];" : "=r"(v) : "l"(p) : "memory");
    return v;
}
__device__ __forceinline__ void st_release_gpu(unsigned* p, unsigned v) {
    asm volatile("st.release.gpu.u32 [%0], %1;" :: "l"(p), "r"(v) : "memory");
}

__global__ __launch_bounds__(256, 1) void rnn_scan(float* __restrict__ out,
                                                   const float* __restrict__ Whh) {
    __shared__ __align__(16) float hs[8 * RSTRIDE];

    const int tid = threadIdx.x;
    const int r   = blockIdx.x & 7;     // rank in group
    const int g   = blockIdx.x >> 3;    // group id (0..15)

    const int j   = tid >> 2;           // 0..63
    const int kq  = tid & 3;            // 0..3
    const int col = r * 64 + j;
    const int k0  = kq * 128;

    // W_hh slice in registers: w2[i] = (Whh[k0+2i][col], Whh[k0+2i+1][col])
    unsigned long long w2[64];
#pragma unroll
    for (int i = 0; i < 64; i++) {
        float lo = Whh[(size_t)(k0 + 2 * i)     * 512 + col];
        float hi = Whh[(size_t)(k0 + 2 * i + 1) * 512 + col];
        w2[i] = pack2(lo, hi);
    }

    // Monotonic flag base: quiescent at launch; only this CTA writes its flag.
    const unsigned base = *(volatile unsigned*)&g_flag[g][r];
    unsigned* const flags = &g_flag[g][0];

    // writer role: kq==0 -> batch 2g, kq==1 -> batch 2g+1
    const int batch = (kq < 2) ? kq : 0;
    float* outp = out + ((size_t)(g * 2 + batch) * SEQ) * DH + col;
    float* const hw[2] = { &g_h[0][g][r][0][0], &g_h[1][g][r][0][0] };

    // stage role: warp w stages rank w's 512B block, 16B per lane
    const int srank = tid >> 5;
    const int sw    = tid & 31;
    const float4* const ssrc[2] = {
        (const float4*)&g_h[0][g][0][0][0] + tid,
        (const float4*)&g_h[1][g][0][0][0] + tid
    };
    float* const sdst = (float*)hs + srank * RSTRIDE + sw * 4;

    // xw prefetch pipeline (one step ahead)
    float xw_next = 0.0f;
    if (kq < 2) xw_next = __ldg(outp);

    for (int t = 0; t < SEQ; ++t) {
        const int cur = t & 1;
        const int nb  = cur ^ 1;

        float xwv = xw_next;
        if (kq < 2 && t + 1 < SEQ) xw_next = __ldg(outp + (size_t)(t + 1) * DH);

        float sum = 0.0f;
        if (t > 0) {
            // Wait: all 8 ranks published o_{t-1} (flag >= base+t).
            // ACQUIRE is load-bearing (stale-sector hazard without it).
            if (tid < 8) {
                const unsigned target = base + (unsigned)t;
                while ((int)(ld_acquire_gpu(flags + tid) - target) < 0) {}
            }
            __syncthreads();
            // Stage 4KB of o_{t-1} from L2 into padded smem.
            float4 v = __ldcg(ssrc[cur]);
            *(float4*)sdst = v;
            __syncthreads();

            const float* hb = hs;
            const ulonglong2* pa0 = (const ulonglong2*)(hb + (2 * kq)     * RSTRIDE);
            const ulonglong2* pa1 = (const ulonglong2*)(hb + (2 * kq + 1) * RSTRIDE);
            const ulonglong2* pb0 = (const ulonglong2*)(hb + (2 * kq)     * RSTRIDE + 64);
            const ulonglong2* pb1 = (const ulonglong2*)(hb + (2 * kq + 1) * RSTRIDE + 64);

            unsigned long long aA0 = 0ULL, aA1 = 0ULL, aB0 = 0ULL, aB1 = 0ULL;
#pragma unroll
            for (int i = 0; i < 16; i++) {
                ulonglong2 xa = pa0[i];
                ulonglong2 xb = pa1[i];
                ulonglong2 ya = pb0[i];
                ulonglong2 yb = pb1[i];
                fma2(aA0, w2[2 * i],          xa.x);
                fma2(aA0, w2[2 * i + 1],      xa.y);
                fma2(aA1, w2[32 + 2 * i],     xb.x);
                fma2(aA1, w2[32 + 2 * i + 1], xb.y);
                fma2(aB0, w2[2 * i],          ya.x);
                fma2(aB0, w2[2 * i + 1],      ya.y);
                fma2(aB1, w2[32 + 2 * i],     yb.x);
                fma2(aB1, w2[32 + 2 * i + 1], yb.y);
            }
            float a0l, a0h, a1l, a1h, b0l, b0h, b1l, b1h;
            unpack2(aA0, a0l, a0h);
            unpack2(aA1, a1l, a1h);
            unpack2(aB0, b0l, b0h);
            unpack2(aB1, b1l, b1h);
            float pA = (a0l + a0h) + (a1l + a1h);
            float pB = (b0l + b0h) + (b1l + b1h);
            // paired 3-shuffle reduction: kq=0 lane -> batch-0 sum, kq=1 -> batch-1
            float u  = (kq & 1) ? pB : pA;
            float v2 = (kq & 1) ? pA : pB;
            u += __shfl_xor_sync(0xffffffffu, v2, 1);
            u += __shfl_xor_sync(0xffffffffu, u, 2);
            sum = u;
        }

        float hn = 0.0f;
        if (kq < 2) {
            hn = tanh_fast(sum + xwv);              // t==0: sum=0
            if (t < SEQ - 1)
                __stcg(hw[nb] + kq * 64 + j, hn);   // publish FIRST (critical)
        }

        if (t < SEQ - 1) {
            __syncthreads();   // all publish stores issued CTA-wide
            if (tid == 0)
                st_release_gpu(flags + r, base + (unsigned)(t + 1));
        }

        // DRAM output store AFTER the release: off the critical path.
        if (kq < 2) outp[(size_t)t * DH] = hn;
    }
}

// ---------------------------------------------------------------------------
// Launch
// ---------------------------------------------------------------------------
extern "C" void kernel_launch(void* const* d_in, const int* in_sizes, int n_in,
                              void* d_out, int out_size) {
    const float* x    = (const float*)d_in[0];  // [32,2048,512]
    const float* W_ih = (const float*)d_in[1];  // [512,512]
    const float* W_hh = (const float*)d_in[2];  // [512,512]
    const float* bias = (const float*)d_in[3];  // [512]
    float* out = (float*)d_out;                 // [32,2048,512]

    // Persistent GEMM: 296 CTAs (2/SM), each ~7 tiles.
    gemm_xw<<<GEMM_CTAS, 256>>>(x, W_ih, bias, out);

    // 128 CTAs = 16 groups x 8 ranks (single wave — required for spin safety).
    rnn_scan<<<128, 256>>>(out, W_hh);
}